// round 3
// baseline (speedup 1.0000x reference)
#include <cuda_runtime.h>
#include <cuda_bf16.h>
#include <math.h>

#define N     8192
#define FIN   256
#define FOUT  64
#define ALPHA 0.2f

// ---------------- scratch (no allocations allowed) ----------------
__device__ float g_Wh[(size_t)N * FOUT];
__device__ float g_s1[N], g_s2[N];
__device__ float g_E1[N], g_F1[N], g_E2[N], g_F2[N];

// ---------------- f32x2 packed-FMA helpers ----------------
__device__ __forceinline__ unsigned long long pack_dup(float x) {
    unsigned long long r;
    asm("mov.b64 %0, {%1, %1};" : "=l"(r) : "f"(x));
    return r;
}
__device__ __forceinline__ unsigned long long ffma2(unsigned long long a,
                                                    unsigned long long b,
                                                    unsigned long long c) {
    unsigned long long d;
    asm("fma.rn.f32x2 %0, %1, %2, %3;" : "=l"(d) : "l"(a), "l"(b), "l"(c));
    return d;
}
__device__ __forceinline__ float2 unpack2(unsigned long long v) {
    float2 f;
    asm("mov.b64 {%0, %1}, %2;" : "=f"(f.x), "=f"(f.y) : "l"(v));
    return f;
}

// ---------------- kernel 1: Wh = h@W, s1/s2, exp vectors ----------------
// 64 blocks x 128 threads; one thread per row.
__global__ void __launch_bounds__(128) k_prep(const float* __restrict__ h,
                                              const float* __restrict__ W,
                                              const float* __restrict__ a) {
    __shared__ __align__(16) float sW[32 * 64];
    __shared__ float sa[2 * FOUT];
    const int t = threadIdx.x;
    const int i = blockIdx.x * 128 + t;

    sa[t] = a[t];  // 128 threads, 128 entries

    float acc[FOUT];
#pragma unroll
    for (int f = 0; f < FOUT; f++) acc[f] = 0.f;

    for (int c = 0; c < 8; c++) {
        __syncthreads();
        // stage 32 rows of W (32x64 f32 = 8KB)
        const float4* Wg = (const float4*)(W + (size_t)c * 32 * 64);
        float4* s4 = (float4*)sW;
#pragma unroll
        for (int q = 0; q < 4; q++) s4[t + q * 128] = Wg[t + q * 128];
        __syncthreads();

        const float4* hrow = (const float4*)(h + (size_t)i * FIN + c * 32);
#pragma unroll
        for (int k4 = 0; k4 < 8; k4++) {
            float4 hv = hrow[k4];
#pragma unroll
            for (int f4 = 0; f4 < 16; f4++) {
                const float* b = sW + (k4 * 4) * 64 + f4 * 4;
                float4 w0 = *(const float4*)(b);
                float4 w1 = *(const float4*)(b + 64);
                float4 w2 = *(const float4*)(b + 128);
                float4 w3 = *(const float4*)(b + 192);
                acc[f4 * 4 + 0] += hv.x * w0.x + hv.y * w1.x + hv.z * w2.x + hv.w * w3.x;
                acc[f4 * 4 + 1] += hv.x * w0.y + hv.y * w1.y + hv.z * w2.y + hv.w * w3.y;
                acc[f4 * 4 + 2] += hv.x * w0.z + hv.y * w1.z + hv.z * w2.z + hv.w * w3.z;
                acc[f4 * 4 + 3] += hv.x * w0.w + hv.y * w1.w + hv.z * w2.w + hv.w * w3.w;
            }
        }
    }

    float s1 = 0.f, s2 = 0.f;
#pragma unroll
    for (int f = 0; f < FOUT; f++) {
        s1 += acc[f] * sa[f];
        s2 += acc[f] * sa[FOUT + f];
    }

    float4* o4 = (float4*)(g_Wh + (size_t)i * FOUT);
#pragma unroll
    for (int f4 = 0; f4 < 16; f4++)
        o4[f4] = make_float4(acc[f4 * 4], acc[f4 * 4 + 1], acc[f4 * 4 + 2], acc[f4 * 4 + 3]);

    g_s1[i] = s1;
    g_s2[i] = s2;
    g_E1[i] = expf(s1);
    g_F1[i] = expf(ALPHA * s1);
    g_E2[i] = expf(s2);
    g_F2[i] = expf(ALPHA * s2);
}

// ---------------- kernel 2: fused masked-softmax attention + P@Wh ----------------
// 128 blocks x 256 threads; block handles 64 rows, loops over j in chunks of 64.
// Thread map: rg = t>>3 (0..31) owns rows rg*2..+1; fg = t&7 owns features fg*8..+7.
// Inner GEMM per kk: 2x LDS.128 (Wh) + 2x LDS.32 (P) + 2 pack movs + 8 FFMA2.
__global__ void __launch_bounds__(256) k_attn(const int* __restrict__ adj,
                                              float* __restrict__ out) {
    __shared__ __align__(16) float sWh[64 * 64];   // [j][f]
    __shared__ __align__(16) float sP[64][68];     // [r][j], padded
    __shared__ float sE2[64], sF2[64], sS2[64];
    __shared__ float sS1[64], sE1[64], sF1[64];
    __shared__ float sDen[64];

    const int t = threadIdx.x;
    const int i0 = blockIdx.x * 64;

    if (t < 64) {
        sS1[t] = g_s1[i0 + t];
        sE1[t] = g_E1[i0 + t];
        sF1[t] = g_F1[i0 + t];
        sDen[t] = 0.f;
    }
    const int rg = t >> 3;        // 0..31
    const int fg = t & 7;         // 0..7
    const int r0 = rg * 2;        // 2 rows per thread
    const int f0 = fg * 8;        // 8 features / 8 j-columns per thread

    unsigned long long acc[8];
#pragma unroll
    for (int q = 0; q < 8; q++) acc[q] = 0ull;
    float dsum0 = 0.f, dsum1 = 0.f;

    // prefetch chunk 0 into registers
    float4 wreg[4];
    int4 areg[4];   // [row0 lo, row0 hi, row1 lo, row1 hi] of adj cols f0..f0+7
    float e2r = 0.f, f2r = 0.f, s2r = 0.f;
    {
        const float4* Wg = (const float4*)(g_Wh);
#pragma unroll
        for (int q = 0; q < 4; q++) wreg[q] = Wg[t + q * 256];
        if (t < 64) { e2r = g_E2[t]; f2r = g_F2[t]; s2r = g_s2[t]; }
#pragma unroll
        for (int q = 0; q < 2; q++) {
            const int* arow = adj + (size_t)(i0 + r0 + q) * N + f0;
            areg[2 * q + 0] = *(const int4*)(arow);
            areg[2 * q + 1] = *(const int4*)(arow + 4);
        }
    }

    for (int jc = 0; jc < N; jc += 64) {
        __syncthreads();  // previous GEMM done reading smem
        {
            float4* s4 = (float4*)sWh;
#pragma unroll
            for (int q = 0; q < 4; q++) s4[t + q * 256] = wreg[q];
            if (t < 64) { sE2[t] = e2r; sF2[t] = f2r; sS2[t] = s2r; }
        }
        __syncthreads();

        // ---- build P tile: rows r0..r0+1, j-columns f0..f0+7 ----
        {
            float s2v[8], e2v[8], f2v[8];
#pragma unroll
            for (int m = 0; m < 8; m++) {
                s2v[m] = sS2[f0 + m];
                e2v[m] = sE2[f0 + m];
                f2v[m] = sF2[f0 + m];
            }
#pragma unroll
            for (int q = 0; q < 2; q++) {
                const int r = r0 + q;
                const float s1r = sS1[r], e1r = sE1[r], f1r = sF1[r];
                const int* av = (const int*)&areg[2 * q];
                float p[8];
                float ds = 0.f;
#pragma unroll
                for (int m = 0; m < 8; m++) {
                    float w = (s1r + s2v[m] > 0.f) ? e1r * e2v[m] : f1r * f2v[m];
                    p[m] = (av[m] != 0) ? w : 0.f;
                    ds += p[m];
                }
                *(float4*)&sP[r][f0]     = make_float4(p[0], p[1], p[2], p[3]);
                *(float4*)&sP[r][f0 + 4] = make_float4(p[4], p[5], p[6], p[7]);
                if (q == 0) dsum0 += ds; else dsum1 += ds;
            }
        }

        // ---- prefetch next chunk (hides DRAM/L2 latency under GEMM) ----
        const int jn = jc + 64;
        if (jn < N) {
            const float4* Wg = (const float4*)(g_Wh + (size_t)jn * FOUT);
#pragma unroll
            for (int q = 0; q < 4; q++) wreg[q] = Wg[t + q * 256];
            if (t < 64) { e2r = g_E2[jn + t]; f2r = g_F2[jn + t]; s2r = g_s2[jn + t]; }
#pragma unroll
            for (int q = 0; q < 2; q++) {
                const int* arow = adj + (size_t)(i0 + r0 + q) * N + jn + f0;
                areg[2 * q + 0] = *(const int4*)(arow);
                areg[2 * q + 1] = *(const int4*)(arow + 4);
            }
        }
        __syncthreads();  // P tile visible

        // ---- register-blocked GEMM: acc += P[r][kk] * Wh[kk][f], f32x2 packed ----
#pragma unroll 8
        for (int kk = 0; kk < 64; kk++) {
            ulonglong2 wA = *(const ulonglong2*)&sWh[kk * 64 + f0];
            ulonglong2 wB = *(const ulonglong2*)&sWh[kk * 64 + f0 + 4];
            unsigned long long pp0 = pack_dup(sP[r0 + 0][kk]);
            unsigned long long pp1 = pack_dup(sP[r0 + 1][kk]);
            acc[0] = ffma2(pp0, wA.x, acc[0]);
            acc[1] = ffma2(pp0, wA.y, acc[1]);
            acc[2] = ffma2(pp0, wB.x, acc[2]);
            acc[3] = ffma2(pp0, wB.y, acc[3]);
            acc[4] = ffma2(pp1, wA.x, acc[4]);
            acc[5] = ffma2(pp1, wA.y, acc[5]);
            acc[6] = ffma2(pp1, wB.x, acc[6]);
            acc[7] = ffma2(pp1, wB.y, acc[7]);
        }
    }

    // ---- denominator reduction ----
    atomicAdd(&sDen[r0 + 0], dsum0);
    atomicAdd(&sDen[r0 + 1], dsum1);
    __syncthreads();

    // ---- epilogue: normalize + ELU + store ----
#pragma unroll
    for (int q = 0; q < 2; q++) {
        const int r = r0 + q;
        const float inv = 1.f / sDen[r];
        float o[8];
#pragma unroll
        for (int p = 0; p < 4; p++) {
            float2 v = unpack2(acc[q * 4 + p]);
            o[2 * p]     = v.x * inv;
            o[2 * p + 1] = v.y * inv;
        }
#pragma unroll
        for (int m = 0; m < 8; m++)
            o[m] = (o[m] > 0.f) ? o[m] : expm1f(o[m]);
        float* orow = out + (size_t)(i0 + r) * FOUT + f0;
        *(float4*)(orow)     = make_float4(o[0], o[1], o[2], o[3]);
        *(float4*)(orow + 4) = make_float4(o[4], o[5], o[6], o[7]);
    }
}

// ---------------- launch ----------------
extern "C" void kernel_launch(void* const* d_in, const int* in_sizes, int n_in,
                              void* d_out, int out_size) {
    // Identify inputs by element count (robust to metadata ordering):
    // h = 8192*256 = 2097152, adj = 8192*8192 = 67108864, W = 256*64 = 16384, a = 128.
    const float* h = nullptr; const int* adj = nullptr;
    const float* W = nullptr; const float* a = nullptr;
    for (int k = 0; k < n_in; k++) {
        switch (in_sizes[k]) {
            case 2097152:  h   = (const float*)d_in[k]; break;
            case 67108864: adj = (const int*)d_in[k];   break;
            case 16384:    W   = (const float*)d_in[k]; break;
            case 128:      a   = (const float*)d_in[k]; break;
        }
    }
    float* out = (float*)d_out;

    k_prep<<<N / 128, 128>>>(h, W, a);
    k_attn<<<N / 64, 256>>>(adj, out);
}

// round 4
// speedup vs baseline: 1.5607x; 1.5607x over previous
#include <cuda_runtime.h>
#include <cuda_bf16.h>
#include <math.h>

#define N     8192
#define FIN   256
#define FOUT  64
#define ALPHA 0.2f
#define JS    4            // j-splits
#define RPB   128          // rows per CTA (k_attn)
#define JCH   64           // j chunk
#define CHUNKS ((N / JS) / JCH)   // 32

// ---------------- scratch ----------------
__device__ float g_Wh[(size_t)N * FOUT];
__device__ float g_s1[N], g_s2[N];
__device__ float g_E1[N], g_F1[N], g_E2[N], g_F2[N];
__device__ float g_pnum[(size_t)JS * N * FOUT];   // partial numerators
__device__ float g_pden[(size_t)JS * N];          // partial denominators

// ---------------- f32x2 helpers ----------------
__device__ __forceinline__ unsigned long long pack_dup(float x) {
    unsigned long long r;
    asm("mov.b64 %0, {%1, %1};" : "=l"(r) : "f"(x));
    return r;
}
__device__ __forceinline__ unsigned long long ffma2(unsigned long long a,
                                                    unsigned long long b,
                                                    unsigned long long c) {
    unsigned long long d;
    asm("fma.rn.f32x2 %0, %1, %2, %3;" : "=l"(d) : "l"(a), "l"(b), "l"(c));
    return d;
}
__device__ __forceinline__ float2 unpack2(unsigned long long v) {
    float2 f;
    asm("mov.b64 {%0, %1}, %2;" : "=f"(f.x), "=f"(f.y) : "l"(v));
    return f;
}

// ---------------- kernel 1: Wh = h@W, s1/s2, exp vectors ----------------
// 128 blocks x 256 threads; block = 64 rows. W fully staged in dynamic smem.
// Thread (r_local = t>>2, fgrp = t&3) computes 16 features of one row.
__global__ void __launch_bounds__(256) k_prep(const float* __restrict__ h,
                                              const float* __restrict__ W,
                                              const float* __restrict__ a) {
    extern __shared__ __align__(16) float sW[];   // 256*64 floats = 64KB
    __shared__ float sa[2 * FOUT];

    const int t = threadIdx.x;
    const int rl = t >> 2;
    const int fgrp = t & 3;
    const int f0 = fgrp * 16;
    const int i = blockIdx.x * 64 + rl;

    {   // stage W (4096 float4, 16 per thread)
        const float4* W4 = (const float4*)W;
        float4* s4 = (float4*)sW;
#pragma unroll
        for (int q = 0; q < 16; q++) s4[t + q * 256] = W4[t + q * 256];
        if (t < 128) sa[t] = a[t];
    }
    __syncthreads();

    float acc[16];
#pragma unroll
    for (int f = 0; f < 16; f++) acc[f] = 0.f;

    const float4* h4 = (const float4*)h + (size_t)i * 64;
    for (int k4 = 0; k4 < 64; k4++) {
        float4 hv = h4[k4];
        const float hk[4] = {hv.x, hv.y, hv.z, hv.w};
#pragma unroll
        for (int kk = 0; kk < 4; kk++) {
            const float* wr = sW + (k4 * 4 + kk) * 64 + f0;
            float4 w0 = *(const float4*)(wr);
            float4 w1 = *(const float4*)(wr + 4);
            float4 w2 = *(const float4*)(wr + 8);
            float4 w3 = *(const float4*)(wr + 12);
            float hkv = hk[kk];
            acc[0]  += hkv * w0.x;  acc[1]  += hkv * w0.y;
            acc[2]  += hkv * w0.z;  acc[3]  += hkv * w0.w;
            acc[4]  += hkv * w1.x;  acc[5]  += hkv * w1.y;
            acc[6]  += hkv * w1.z;  acc[7]  += hkv * w1.w;
            acc[8]  += hkv * w2.x;  acc[9]  += hkv * w2.y;
            acc[10] += hkv * w2.z;  acc[11] += hkv * w2.w;
            acc[12] += hkv * w3.x;  acc[13] += hkv * w3.y;
            acc[14] += hkv * w3.z;  acc[15] += hkv * w3.w;
        }
    }

    // s1/s2 partials over this thread's 16 features, reduce across 4 fgrp lanes
    float s1p = 0.f, s2p = 0.f;
#pragma unroll
    for (int f = 0; f < 16; f++) {
        s1p += acc[f] * sa[f0 + f];
        s2p += acc[f] * sa[FOUT + f0 + f];
    }
    s1p += __shfl_xor_sync(0xffffffff, s1p, 1);
    s1p += __shfl_xor_sync(0xffffffff, s1p, 2);
    s2p += __shfl_xor_sync(0xffffffff, s2p, 1);
    s2p += __shfl_xor_sync(0xffffffff, s2p, 2);

    float4* o4 = (float4*)(g_Wh + (size_t)i * FOUT + f0);
    o4[0] = make_float4(acc[0], acc[1], acc[2], acc[3]);
    o4[1] = make_float4(acc[4], acc[5], acc[6], acc[7]);
    o4[2] = make_float4(acc[8], acc[9], acc[10], acc[11]);
    o4[3] = make_float4(acc[12], acc[13], acc[14], acc[15]);

    if (fgrp == 0) {
        g_s1[i] = s1p;
        g_s2[i] = s2p;
        g_E1[i] = expf(s1p);
        g_F1[i] = expf(ALPHA * s1p);
        g_E2[i] = expf(s2p);
        g_F2[i] = expf(ALPHA * s2p);
    }
}

// ---------------- kernel 2: fused attention partials ----------------
// 256 blocks (64 row-blocks x 4 j-splits) x 256 threads, 2 CTAs/SM.
// Block: 128 rows x 64-feature output, j over 2048 cols in chunks of 64.
// GEMM map: rgg=t>>3 -> rows rgg*4; fg=t&7 -> feats fg*8. 32 FMAs/kk/thread.
// Build map: rb0=(t&31)*4 rows; jb=t>>5 -> j-cols jb*8..+7.
// P stored transposed sPT[kk][r] so GEMM reads it as one LDS.128.
__global__ void __launch_bounds__(256, 2) k_attn(const int* __restrict__ adj) {
    extern __shared__ __align__(16) float dyn[];
    float* sWh = dyn;              // [64][64]   16KB
    float* sPT = dyn + 64 * 64;    // [64][132]  33.8KB (pad 132 keeps 16B align)
    __shared__ float sS1[RPB], sE1[RPB], sF1[RPB], sDen[RPB];
    __shared__ float sE2[JCH], sF2[JCH], sS2[JCH];

    const int t = threadIdx.x;
    const int rb_blk = blockIdx.x & 63;
    const int split  = blockIdx.x >> 6;
    const int i0 = rb_blk * RPB;
    const int j0 = split * (N / JS);

    if (t < RPB) {
        sS1[t] = g_s1[i0 + t];
        sE1[t] = g_E1[i0 + t];
        sF1[t] = g_F1[i0 + t];
        sDen[t] = 0.f;
    }

    // GEMM map
    const int r0 = (t >> 3) * 4;
    const int f0 = (t & 7) * 8;
    // build map
    const int rb0 = (t & 31) * 4;
    const int jb  = t >> 5;

    unsigned long long acc[16];
#pragma unroll
    for (int q = 0; q < 16; q++) acc[q] = 0ull;
    float dsum[4] = {0.f, 0.f, 0.f, 0.f};

    // prefetch chunk 0
    float4 wreg[4];
    int areg[4][8];
    float e2r = 0.f, f2r = 0.f, s2r = 0.f;
    {
        const float4* Wg = (const float4*)(g_Wh + (size_t)j0 * FOUT);
#pragma unroll
        for (int q = 0; q < 4; q++) wreg[q] = Wg[t + q * 256];
        if (t < JCH) { e2r = g_E2[j0 + t]; f2r = g_F2[j0 + t]; s2r = g_s2[j0 + t]; }
#pragma unroll
        for (int q = 0; q < 4; q++) {
            const int* arow = adj + (size_t)(i0 + rb0 + q) * N + j0 + jb * 8;
            *(int4*)&areg[q][0] = *(const int4*)(arow);
            *(int4*)&areg[q][4] = *(const int4*)(arow + 4);
        }
    }

    for (int c = 0; c < CHUNKS; c++) {
        __syncthreads();   // prev GEMM done with sWh/sPT
        {
            float4* s4 = (float4*)sWh;
#pragma unroll
            for (int q = 0; q < 4; q++) s4[t + q * 256] = wreg[q];
            if (t < JCH) { sE2[t] = e2r; sF2[t] = f2r; sS2[t] = s2r; }
        }
        __syncthreads();

        // ---- build transposed P tile ----
#pragma unroll
        for (int m = 0; m < 8; m++) {
            const int kk = jb * 8 + m;
            const float s2v = sS2[kk], e2v = sE2[kk], f2v = sF2[kk];
            float p[4];
#pragma unroll
            for (int q = 0; q < 4; q++) {
                const int r = rb0 + q;
                float w = (sS1[r] + s2v > 0.f) ? sE1[r] * e2v : sF1[r] * f2v;
                p[q] = (areg[q][m] != 0) ? w : 0.f;
                dsum[q] += p[q];
            }
            *(float4*)&sPT[kk * 132 + rb0] = make_float4(p[0], p[1], p[2], p[3]);
        }

        // ---- prefetch next chunk ----
        if (c + 1 < CHUNKS) {
            const int jn = j0 + (c + 1) * JCH;
            const float4* Wg = (const float4*)(g_Wh + (size_t)jn * FOUT);
#pragma unroll
            for (int q = 0; q < 4; q++) wreg[q] = Wg[t + q * 256];
            if (t < JCH) { e2r = g_E2[jn + t]; f2r = g_F2[jn + t]; s2r = g_s2[jn + t]; }
#pragma unroll
            for (int q = 0; q < 4; q++) {
                const int* arow = adj + (size_t)(i0 + rb0 + q) * N + jn + jb * 8;
                *(int4*)&areg[q][0] = *(const int4*)(arow);
                *(int4*)&areg[q][4] = *(const int4*)(arow + 4);
            }
        }
        __syncthreads();   // P tile + Wh visible

        // ---- GEMM: acc[4 rows][8 feats] += P^T[kk][r] * Wh[kk][f] ----
#pragma unroll 8
        for (int kk = 0; kk < JCH; kk++) {
            float4 pt = *(const float4*)&sPT[kk * 132 + r0];
            ulonglong2 wA = *(const ulonglong2*)&sWh[kk * 64 + f0];
            ulonglong2 wB = *(const ulonglong2*)&sWh[kk * 64 + f0 + 4];
            unsigned long long p0 = pack_dup(pt.x);
            unsigned long long p1 = pack_dup(pt.y);
            unsigned long long p2 = pack_dup(pt.z);
            unsigned long long p3 = pack_dup(pt.w);
            acc[0]  = ffma2(p0, wA.x, acc[0]);
            acc[1]  = ffma2(p0, wA.y, acc[1]);
            acc[2]  = ffma2(p0, wB.x, acc[2]);
            acc[3]  = ffma2(p0, wB.y, acc[3]);
            acc[4]  = ffma2(p1, wA.x, acc[4]);
            acc[5]  = ffma2(p1, wA.y, acc[5]);
            acc[6]  = ffma2(p1, wB.x, acc[6]);
            acc[7]  = ffma2(p1, wB.y, acc[7]);
            acc[8]  = ffma2(p2, wA.x, acc[8]);
            acc[9]  = ffma2(p2, wA.y, acc[9]);
            acc[10] = ffma2(p2, wB.x, acc[10]);
            acc[11] = ffma2(p2, wB.y, acc[11]);
            acc[12] = ffma2(p3, wA.x, acc[12]);
            acc[13] = ffma2(p3, wA.y, acc[13]);
            acc[14] = ffma2(p3, wB.x, acc[14]);
            acc[15] = ffma2(p3, wB.y, acc[15]);
        }
    }

    // ---- denominators (build-map rows) ----
#pragma unroll
    for (int q = 0; q < 4; q++) atomicAdd(&sDen[rb0 + q], dsum[q]);
    __syncthreads();
    if (t < RPB) g_pden[(size_t)split * N + i0 + t] = sDen[t];

    // ---- raw numerator partials (GEMM-map rows) ----
#pragma unroll
    for (int q = 0; q < 4; q++) {
        const int r = r0 + q;
        float2 v0 = unpack2(acc[q * 4 + 0]);
        float2 v1 = unpack2(acc[q * 4 + 1]);
        float2 v2 = unpack2(acc[q * 4 + 2]);
        float2 v3 = unpack2(acc[q * 4 + 3]);
        float* orow = g_pnum + ((size_t)split * N + i0 + r) * FOUT + f0;
        *(float4*)(orow)     = make_float4(v0.x, v0.y, v1.x, v1.y);
        *(float4*)(orow + 4) = make_float4(v2.x, v2.y, v3.x, v3.y);
    }
}

// ---------------- kernel 3: combine splits + normalize + ELU ----------------
// 512 blocks x 256 threads; one float4 of output per thread.
__global__ void __launch_bounds__(256) k_reduce(float* __restrict__ out) {
    const int idx = blockIdx.x * 256 + threadIdx.x;
    const int i = idx >> 4;
    const int fq = idx & 15;

    float4 s = make_float4(0.f, 0.f, 0.f, 0.f);
    float den = 0.f;
#pragma unroll
    for (int sp = 0; sp < JS; sp++) {
        const float4 v = *(const float4*)(g_pnum + ((size_t)sp * N + i) * FOUT + fq * 4);
        s.x += v.x; s.y += v.y; s.z += v.z; s.w += v.w;
        den += g_pden[(size_t)sp * N + i];
    }
    const float inv = 1.f / den;
    float o0 = s.x * inv, o1 = s.y * inv, o2 = s.z * inv, o3 = s.w * inv;
    o0 = (o0 > 0.f) ? o0 : expm1f(o0);
    o1 = (o1 > 0.f) ? o1 : expm1f(o1);
    o2 = (o2 > 0.f) ? o2 : expm1f(o2);
    o3 = (o3 > 0.f) ? o3 : expm1f(o3);
    *(float4*)(out + (size_t)i * FOUT + fq * 4) = make_float4(o0, o1, o2, o3);
}

// ---------------- launch ----------------
extern "C" void kernel_launch(void* const* d_in, const int* in_sizes, int n_in,
                              void* d_out, int out_size) {
    const float* h = nullptr; const int* adj = nullptr;
    const float* W = nullptr; const float* a = nullptr;
    for (int k = 0; k < n_in; k++) {
        switch (in_sizes[k]) {
            case 2097152:  h   = (const float*)d_in[k]; break;
            case 67108864: adj = (const int*)d_in[k];   break;
            case 16384:    W   = (const float*)d_in[k]; break;
            case 128:      a   = (const float*)d_in[k]; break;
        }
    }
    float* out = (float*)d_out;

    static int attr_done = 0;
    if (!attr_done) {
        cudaFuncSetAttribute(k_prep, cudaFuncAttributeMaxDynamicSharedMemorySize, 65536);
        cudaFuncSetAttribute(k_attn, cudaFuncAttributeMaxDynamicSharedMemorySize, 50176);
        attr_done = 1;
    }

    k_prep<<<N / 64, 256, 65536>>>(h, W, a);
    k_attn<<<64 * JS, 256, 50176>>>(adj);
    k_reduce<<<(N * FOUT / 4) / 256, 256>>>(out);
}

// round 14
// speedup vs baseline: 4.3221x; 2.7693x over previous
#include <cuda_runtime.h>
#include <cuda_bf16.h>
#include <stdint.h>
#include <math.h>

#define N     8192
#define FIN   256
#define FOUT  64
#define ALPHA 0.2f
#define JS    4
#define RPB   128
#define JCH   64
#define CHUNKS ((N / JS) / JCH)   // 32
#define PK    72                  // bf16 pitch: 144B -> rows 4 banks apart, ldmatrix conflict-free

// ---------------- scratch ----------------
__device__ __nv_bfloat16 g_WhbT[(size_t)FOUT * N];   // [f][j] bf16
__device__ float g_s1[N], g_s2[N];
__device__ float g_E1[N], g_F1[N], g_E2[N], g_F2[N];
__device__ float g_pnum[(size_t)JS * N * FOUT];
__device__ float g_pden[(size_t)JS * N];

// ---------------- helpers ----------------
__device__ __forceinline__ unsigned long long pack_dup(float x) {
    unsigned long long r; asm("mov.b64 %0, {%1, %1};" : "=l"(r) : "f"(x)); return r;
}
__device__ __forceinline__ unsigned long long ffma2(unsigned long long a,
                                                    unsigned long long b,
                                                    unsigned long long c) {
    unsigned long long d;
    asm("fma.rn.f32x2 %0, %1, %2, %3;" : "=l"(d) : "l"(a), "l"(b), "l"(c));
    return d;
}
__device__ __forceinline__ float2 unpack2(unsigned long long v) {
    float2 f; asm("mov.b64 {%0, %1}, %2;" : "=f"(f.x), "=f"(f.y) : "l"(v)); return f;
}
__device__ __forceinline__ uint32_t smem_u32(const void* p) {
    uint32_t a;
    asm("{ .reg .u64 t; cvta.to.shared.u64 t, %1; cvt.u32.u64 %0, t; }" : "=r"(a) : "l"(p));
    return a;
}
__device__ __forceinline__ uint32_t bf16x2_pack(float lo, float hi) {
    uint32_t r;
    asm("cvt.rn.satfinite.bf16x2.f32 %0, %1, %2;" : "=r"(r) : "f"(hi), "f"(lo));
    return r;
}
__device__ __forceinline__ void ldsm_x4(uint32_t& r0, uint32_t& r1, uint32_t& r2, uint32_t& r3,
                                        uint32_t addr) {
    asm volatile("ldmatrix.sync.aligned.m8n8.x4.shared.b16 {%0,%1,%2,%3}, [%4];"
                 : "=r"(r0), "=r"(r1), "=r"(r2), "=r"(r3) : "r"(addr));
}
__device__ __forceinline__ void mma_16816(float& d0, float& d1, float& d2, float& d3,
                                          uint32_t a0, uint32_t a1, uint32_t a2, uint32_t a3,
                                          uint32_t b0, uint32_t b1) {
    asm volatile(
        "mma.sync.aligned.m16n8k16.row.col.f32.bf16.bf16.f32 "
        "{%0,%1,%2,%3}, {%4,%5,%6,%7}, {%8,%9}, {%0,%1,%2,%3};"
        : "+f"(d0), "+f"(d1), "+f"(d2), "+f"(d3)
        : "r"(a0), "r"(a1), "r"(a2), "r"(a3), "r"(b0), "r"(b1));
}

// ---------------- kernel 1: Wh = h@W + s1/s2/exp + WhT bf16 (measured 41.6us) ----------------
__global__ void __launch_bounds__(256) k_prep(const float* __restrict__ h,
                                              const float* __restrict__ W,
                                              const float* __restrict__ a) {
    __shared__ __align__(16) float sHT[64 * 68];
    __shared__ __align__(16) float sWc[64 * 64];
    __shared__ float sa[2 * FOUT];
    __shared__ float sS1a[64], sS2a[64];

    const int t = threadIdx.x;
    const int i0 = blockIdx.x * 64;

    if (t < 128) sa[t] = a[t];
    if (t < 64) { sS1a[t] = 0.f; sS2a[t] = 0.f; }

    const int r0 = (t >> 3) * 2;
    const int f0 = (t & 7) * 8;
    const int lrow = t >> 2;
    const int kseg = t & 3;

    unsigned long long acc[8];
#pragma unroll
    for (int q = 0; q < 8; q++) acc[q] = 0ull;

    for (int kc = 0; kc < FIN; kc += 64) {
        __syncthreads();
        {
            const float4* hr = (const float4*)(h + (size_t)(i0 + lrow) * FIN + kc + kseg * 16);
#pragma unroll
            for (int v = 0; v < 4; v++) {
                float4 hv = hr[v];
                const int kb = kseg * 16 + v * 4;
                sHT[(kb + 0) * 68 + lrow] = hv.x;
                sHT[(kb + 1) * 68 + lrow] = hv.y;
                sHT[(kb + 2) * 68 + lrow] = hv.z;
                sHT[(kb + 3) * 68 + lrow] = hv.w;
            }
        }
        {
            const float4* wr = (const float4*)(W + (size_t)(kc + (t >> 2)) * FOUT + (t & 3) * 16);
            float4* sw = (float4*)(sWc + (t >> 2) * 64 + (t & 3) * 16);
#pragma unroll
            for (int v = 0; v < 4; v++) sw[v] = wr[v];
        }
        __syncthreads();

#pragma unroll 8
        for (int kk = 0; kk < 64; kk++) {
            float2 pt = *(const float2*)&sHT[kk * 68 + r0];
            ulonglong2 wA = *(const ulonglong2*)&sWc[kk * 64 + f0];
            ulonglong2 wB = *(const ulonglong2*)&sWc[kk * 64 + f0 + 4];
            unsigned long long p0 = pack_dup(pt.x);
            unsigned long long p1 = pack_dup(pt.y);
            acc[0] = ffma2(p0, wA.x, acc[0]);
            acc[1] = ffma2(p0, wA.y, acc[1]);
            acc[2] = ffma2(p0, wB.x, acc[2]);
            acc[3] = ffma2(p0, wB.y, acc[3]);
            acc[4] = ffma2(p1, wA.x, acc[4]);
            acc[5] = ffma2(p1, wA.y, acc[5]);
            acc[6] = ffma2(p1, wB.x, acc[6]);
            acc[7] = ffma2(p1, wB.y, acc[7]);
        }
    }

#pragma unroll
    for (int q = 0; q < 2; q++) {
        float o[8];
#pragma unroll
        for (int p = 0; p < 4; p++) {
            float2 v = unpack2(acc[q * 4 + p]);
            o[2 * p] = v.x; o[2 * p + 1] = v.y;
        }
        float s1p = 0.f, s2p = 0.f;
#pragma unroll
        for (int m = 0; m < 8; m++) {
            s1p += o[m] * sa[f0 + m];
            s2p += o[m] * sa[FOUT + f0 + m];
        }
        atomicAdd(&sS1a[r0 + q], s1p);
        atomicAdd(&sS2a[r0 + q], s2p);
        const int i = i0 + r0 + q;
#pragma unroll
        for (int m = 0; m < 8; m++)
            g_WhbT[(size_t)(f0 + m) * N + i] = __float2bfloat16(o[m]);
    }
    __syncthreads();

    if (t < 64) {
        const float s1 = sS1a[t], s2 = sS2a[t];
        const int i = i0 + t;
        g_s1[i] = s1; g_s2[i] = s2;
        g_E1[i] = expf(s1);        g_F1[i] = expf(ALPHA * s1);
        g_E2[i] = expf(s2);        g_F2[i] = expf(ALPHA * s2);
    }
}

// ---------------- kernel 2: P-build + mma.sync bf16 GEMM ----------------
// grid 256 (64 row-blocks x 4 splits) x 256 threads, 2 CTAs/SM.
// Dyn smem: sP[128][PK] bf16 (18432B) @0 ; sWhT[64][PK] bf16 (9216B) @18432.
// Warp w owns D rows w*16..+15; acc 8 n-tiles x 4 f32, carried across chunks.
__global__ void __launch_bounds__(256, 2) k_attn(const int* __restrict__ adj) {
    extern __shared__ __align__(16) char sm[];
    __nv_bfloat16* sP   = (__nv_bfloat16*)sm;            // [128][PK]
    __nv_bfloat16* sWhT = (__nv_bfloat16*)(sm + 18432);  // [64][PK]
    __shared__ float sS2[JCH], sE2[JCH], sF2[JCH];
    __shared__ float sDen[RPB];

    const int t = threadIdx.x;
    const int wid = t >> 5;
    const int lane = t & 31;
    const int rb_blk = blockIdx.x & 63;
    const int split  = blockIdx.x >> 6;
    const int i0 = rb_blk * RPB;
    const int j0 = split * (N / JS);

    if (t < RPB) sDen[t] = 0.f;

    // build map: one row, half the k-chunk
    const int brow = t >> 1;
    const int k0b = (t & 1) * 32;
    const float s1r = g_s1[i0 + brow];
    const float e1r = g_E1[i0 + brow];
    const float f1r = g_F1[i0 + brow];
    float dsum = 0.f;

    // MMA maps
    const int m0 = wid * 16;
    const uint32_t sP_u32   = smem_u32(sP);
    const uint32_t sWhT_u32 = smem_u32(sWhT);
    // A ldmatrix: rows m0 + (lane&15), k-offset (lane>>4)*8  (+ks*16 per step)
    const uint32_t aAddrBase = sP_u32 + ((m0 + (lane & 15)) * PK + ((lane >> 4) << 3)) * 2;
    // B ldmatrix: n = ((lane>>4)&1)*8 + (lane&7), k-offset ((lane>>3)&1)*8
    const uint32_t bAddrBase = sWhT_u32 +
        (((((lane >> 4) & 1) << 3) + (lane & 7)) * PK + (((lane >> 3) & 1) << 3)) * 2;

    float dacc[8][4];
#pragma unroll
    for (int nt = 0; nt < 8; nt++)
#pragma unroll
        for (int q = 0; q < 4; q++) dacc[nt][q] = 0.f;

    // prefetch chunk 0
    int4 areg[8];
    int4 breg[2];
    float e2r = 0.f, f2r = 0.f, s2r = 0.f;
    {
        const int4* arow = (const int4*)(adj + (size_t)(i0 + brow) * N + j0 + k0b);
#pragma unroll
        for (int q = 0; q < 8; q++) areg[q] = arow[q];
        const char* bp = (const char*)g_WhbT + (((size_t)(t >> 2) * N + j0) * 2 + (t & 3) * 32);
        breg[0] = *(const int4*)(bp);
        breg[1] = *(const int4*)(bp + 16);
        if (t < JCH) { e2r = g_E2[j0 + t]; f2r = g_F2[j0 + t]; s2r = g_s2[j0 + t]; }
    }

    for (int c = 0; c < CHUNKS; c++) {
        __syncthreads();   // prev MMA done reading tiles
        if (t < JCH) { sE2[t] = e2r; sF2[t] = f2r; sS2[t] = s2r; }

        // ---- store B tile: sWhT[f][k], f = t>>2, k-offset (t&3)*16 ----
        {
            __nv_bfloat16* dst = sWhT + (t >> 2) * PK + (t & 3) * 16;
            *(int4*)(dst)     = breg[0];
            *(int4*)(dst + 8) = breg[1];
        }
        __syncthreads();   // sE2/sF2/sS2 + B tile visible

        // ---- build P row-slice -> bf16 -> sP ----
#pragma unroll
        for (int g = 0; g < 4; g++) {
            const int kb = k0b + g * 8;
            float4 s2a = *(const float4*)&sS2[kb];
            float4 s2b = *(const float4*)&sS2[kb + 4];
            float4 e2a = *(const float4*)&sE2[kb];
            float4 e2b = *(const float4*)&sE2[kb + 4];
            float4 f2a = *(const float4*)&sF2[kb];
            float4 f2b = *(const float4*)&sF2[kb + 4];
            const int* av = (const int*)&areg[g * 2];
            const float s2v[8] = {s2a.x, s2a.y, s2a.z, s2a.w, s2b.x, s2b.y, s2b.z, s2b.w};
            const float e2v[8] = {e2a.x, e2a.y, e2a.z, e2a.w, e2b.x, e2b.y, e2b.z, e2b.w};
            const float f2v[8] = {f2a.x, f2a.y, f2a.z, f2a.w, f2b.x, f2b.y, f2b.z, f2b.w};
            float p[8];
#pragma unroll
            for (int m = 0; m < 8; m++) {
                float w = (s1r + s2v[m] > 0.f) ? e1r * e2v[m] : f1r * f2v[m];
                p[m] = (av[m] != 0) ? w : 0.f;
                dsum += p[m];
            }
            uint4 pk;
            pk.x = bf16x2_pack(p[0], p[1]);
            pk.y = bf16x2_pack(p[2], p[3]);
            pk.z = bf16x2_pack(p[4], p[5]);
            pk.w = bf16x2_pack(p[6], p[7]);
            *(uint4*)(sP + brow * PK + kb) = pk;
        }

        // ---- prefetch chunk c+1 ----
        if (c + 1 < CHUNKS) {
            const int jn = j0 + (c + 1) * JCH;
            const int4* arow = (const int4*)(adj + (size_t)(i0 + brow) * N + jn + k0b);
#pragma unroll
            for (int q = 0; q < 8; q++) areg[q] = arow[q];
            const char* bp = (const char*)g_WhbT + (((size_t)(t >> 2) * N + jn) * 2 + (t & 3) * 32);
            breg[0] = *(const int4*)(bp);
            breg[1] = *(const int4*)(bp + 16);
            if (t < JCH) { e2r = g_E2[jn + t]; f2r = g_F2[jn + t]; s2r = g_s2[jn + t]; }
        }
        __syncthreads();   // P tile visible

        // ---- MMA: 4 k-steps x (1 A-ldsm + 4 B-ldsm + 8 mma) ----
#pragma unroll
        for (int ks = 0; ks < 4; ks++) {
            const uint32_t kadd = (uint32_t)(ks * 16 * 2);
            uint32_t a0, a1, a2, a3;
            ldsm_x4(a0, a1, a2, a3, aAddrBase + kadd);
#pragma unroll
            for (int ntp = 0; ntp < 4; ntp++) {
                uint32_t b0, b1, b2, b3;
                ldsm_x4(b0, b1, b2, b3, bAddrBase + (uint32_t)(ntp * 16 * PK * 2) + kadd);
                float* d0 = dacc[ntp * 2];
                float* d1 = dacc[ntp * 2 + 1];
                mma_16816(d0[0], d0[1], d0[2], d0[3], a0, a1, a2, a3, b0, b1);
                mma_16816(d1[0], d1[1], d1[2], d1[3], a0, a1, a2, a3, b2, b3);
            }
        }
    }

    // ---- denominators ----
    atomicAdd(&sDen[brow], dsum);
    __syncthreads();
    if (t < RPB) g_pden[(size_t)split * N + i0 + t] = sDen[t];

    // ---- epilogue: D fragments -> g_pnum ----
    {
        const int r1 = m0 + (lane >> 2);
        const int r2 = r1 + 8;
        const int cb = (lane & 3) * 2;
        float* base1 = g_pnum + ((size_t)split * N + i0 + r1) * FOUT;
        float* base2 = g_pnum + ((size_t)split * N + i0 + r2) * FOUT;
#pragma unroll
        for (int nt = 0; nt < 8; nt++) {
            const int col = nt * 8 + cb;
            *(float2*)(base1 + col) = make_float2(dacc[nt][0], dacc[nt][1]);
            *(float2*)(base2 + col) = make_float2(dacc[nt][2], dacc[nt][3]);
        }
    }
}

// ---------------- kernel 3: combine splits + normalize + ELU ----------------
__global__ void __launch_bounds__(256) k_reduce(float* __restrict__ out) {
    const int idx = blockIdx.x * 256 + threadIdx.x;
    const int i = idx >> 4;
    const int fq = idx & 15;

    float4 s = make_float4(0.f, 0.f, 0.f, 0.f);
    float den = 0.f;
#pragma unroll
    for (int sp = 0; sp < JS; sp++) {
        const float4 v = *(const float4*)(g_pnum + ((size_t)sp * N + i) * FOUT + fq * 4);
        s.x += v.x; s.y += v.y; s.z += v.z; s.w += v.w;
        den += g_pden[(size_t)sp * N + i];
    }
    const float inv = 1.f / den;
    float o0 = s.x * inv, o1 = s.y * inv, o2 = s.z * inv, o3 = s.w * inv;
    o0 = (o0 > 0.f) ? o0 : expm1f(o0);
    o1 = (o1 > 0.f) ? o1 : expm1f(o1);
    o2 = (o2 > 0.f) ? o2 : expm1f(o2);
    o3 = (o3 > 0.f) ? o3 : expm1f(o3);
    *(float4*)(out + (size_t)i * FOUT + fq * 4) = make_float4(o0, o1, o2, o3);
}

// ---------------- launch ----------------
extern "C" void kernel_launch(void* const* d_in, const int* in_sizes, int n_in,
                              void* d_out, int out_size) {
    const float* h = nullptr; const int* adj = nullptr;
    const float* W = nullptr; const float* a = nullptr;
    for (int k = 0; k < n_in; k++) {
        switch (in_sizes[k]) {
            case 2097152:  h   = (const float*)d_in[k]; break;
            case 67108864: adj = (const int*)d_in[k];   break;
            case 16384:    W   = (const float*)d_in[k]; break;
            case 128:      a   = (const float*)d_in[k]; break;
        }
    }
    float* out = (float*)d_out;

    cudaFuncSetAttribute(k_attn, cudaFuncAttributeMaxDynamicSharedMemorySize, 28672);

    k_prep<<<N / 64, 256>>>(h, W, a);
    k_attn<<<64 * JS, 256, 28672>>>(adj);
    k_reduce<<<(N * FOUT / 4) / 256, 256>>>(out);
}